// round 5
// baseline (speedup 1.0000x reference)
#include <cuda_runtime.h>

#define BATCH   64
#define HID     1024
#define EMBED   512
#define MAXLEN  1024
#define VOCAB   50257
#define XDIM    (EMBED + HID)      // 1536
#define G3      (3 * HID)          // 3072
#define OUT_OFF (BATCH * VOCAB)    // 3216448
#define NPART   16                 // j-chunks for attention scores

// ------------- scratch (device globals; NEVER passed from host) -------------
__device__ float g_db[BATCH * HID];
__device__ float g_e_part[NPART * MAXLEN * BATCH];
__device__ float g_c[BATCH * HID];
__device__ float g_x[BATCH * XDIM];
__device__ float g_gi[BATCH * G3];
__device__ float g_gh[BATCH * G3];
__device__ float g_h0[BATCH * HID];
__device__ float g_h1[BATCH * HID];

// buffer tags so scratch pointers are resolved IN DEVICE CODE
#define BUF_PARAM 0
#define BUF_X     1
#define BUF_H0    2
#define BUF_H1    3
#define BUF_GI    1
#define BUF_GH    2

// ===========================================================================
// db[b][j] = sum_k dec[b][k] * w1d[k][j]   (dec = state[1], w1d = w_att1[HID:])
// ===========================================================================
__global__ __launch_bounds__(256) void db_kernel(
    const float* __restrict__ state, const float* __restrict__ w_att1)
{
    int idx = blockIdx.x * 256 + threadIdx.x;   // 0..65535
    int b = idx >> 10;
    int j = idx & 1023;
    const float* dec = state + BATCH * HID;            // layer 1
    const float* w1d = w_att1 + (size_t)HID * HID;     // rows HID..2*HID-1
    float acc = 0.f;
#pragma unroll 8
    for (int k = 0; k < HID; ++k)
        acc += dec[b * HID + k] * w1d[(size_t)k * HID + j];
    g_db[idx] = acc;
}

// ===========================================================================
// Attention scores: e_part[jchunk][t][b] = sum_{j in chunk} w2[j]*tanh(S+db)
// S = enc[t] @ w1_e, tile 64(b) x 64(j), K=1024.
// ===========================================================================
__global__ __launch_bounds__(256) void scores_kernel(
    const float* __restrict__ enc, const float* __restrict__ w_att1,
    const float* __restrict__ w_att2)
{
    int t  = blockIdx.y;
    int j0 = blockIdx.x * 64;

    __shared__ float sA[64][65];   // [b][k]
    __shared__ float sB[64][65];   // [k][j]
    __shared__ float red[64][17];

    int tid = threadIdx.x;
    int tx = tid & 15;             // j groups
    int ty = tid >> 4;             // b groups
    float acc[4][4];
#pragma unroll
    for (int i = 0; i < 4; ++i)
#pragma unroll
        for (int j = 0; j < 4; ++j) acc[i][j] = 0.f;

    const float* encT = enc + (size_t)t * (BATCH * HID);

    for (int kk0 = 0; kk0 < HID; kk0 += 64) {
        for (int i = tid; i < 64 * 64; i += 256) {
            int r = i >> 6;
            int c = i & 63;
            sA[r][c] = encT[(size_t)r * HID + kk0 + c];
            sB[r][c] = w_att1[(size_t)(kk0 + r) * HID + j0 + c];
        }
        __syncthreads();
#pragma unroll 8
        for (int k = 0; k < 64; ++k) {
            float a0 = sA[ty * 4 + 0][k];
            float a1 = sA[ty * 4 + 1][k];
            float a2 = sA[ty * 4 + 2][k];
            float a3 = sA[ty * 4 + 3][k];
            float b0 = sB[k][tx * 4 + 0];
            float b1 = sB[k][tx * 4 + 1];
            float b2 = sB[k][tx * 4 + 2];
            float b3 = sB[k][tx * 4 + 3];
            acc[0][0] += a0 * b0; acc[0][1] += a0 * b1; acc[0][2] += a0 * b2; acc[0][3] += a0 * b3;
            acc[1][0] += a1 * b0; acc[1][1] += a1 * b1; acc[1][2] += a1 * b2; acc[1][3] += a1 * b3;
            acc[2][0] += a2 * b0; acc[2][1] += a2 * b1; acc[2][2] += a2 * b2; acc[2][3] += a2 * b3;
            acc[3][0] += a3 * b0; acc[3][1] += a3 * b1; acc[3][2] += a3 * b2; acc[3][3] += a3 * b3;
        }
        __syncthreads();
    }

    float part[4] = {0.f, 0.f, 0.f, 0.f};
#pragma unroll
    for (int j = 0; j < 4; ++j) {
        int jj = j0 + tx * 4 + j;
        float wj = w_att2[jj];
#pragma unroll
        for (int i = 0; i < 4; ++i) {
            int b = ty * 4 + i;
            part[i] += wj * tanhf(acc[i][j] + g_db[b * HID + jj]);
        }
    }
#pragma unroll
    for (int i = 0; i < 4; ++i) red[ty * 4 + i][tx] = part[i];
    __syncthreads();
    if (tid < 64) {
        float s = 0.f;
#pragma unroll
        for (int x = 0; x < 16; ++x) s += red[tid][x];
        g_e_part[(size_t)blockIdx.x * (MAXLEN * BATCH) + t * BATCH + tid] = s;
    }
}

// ===========================================================================
// softmax over t (per b) + context c[b][k] = sum_t alpha[t][b]*enc[t][b][k]
// ===========================================================================
__global__ __launch_bounds__(256) void softmax_ctx_kernel(const float* __restrict__ enc)
{
    int b  = blockIdx.y;
    int k0 = blockIdx.x * 256;
    int tid = threadIdx.x;
    __shared__ float sa[MAXLEN];
    __shared__ float rbuf[256];

    float lm = -1e30f;
    for (int t = tid; t < MAXLEN; t += 256) {
        float v = 0.f;
#pragma unroll
        for (int p = 0; p < NPART; ++p)
            v += g_e_part[(size_t)p * (MAXLEN * BATCH) + t * BATCH + b];
        sa[t] = v;
        lm = fmaxf(lm, v);
    }
    rbuf[tid] = lm; __syncthreads();
    for (int s = 128; s > 0; s >>= 1) {
        if (tid < s) rbuf[tid] = fmaxf(rbuf[tid], rbuf[tid + s]);
        __syncthreads();
    }
    float m = rbuf[0];
    __syncthreads();

    float ls = 0.f;
    for (int t = tid; t < MAXLEN; t += 256) {
        float v = expf(sa[t] - m);
        sa[t] = v;
        ls += v;
    }
    rbuf[tid] = ls; __syncthreads();
    for (int s = 128; s > 0; s >>= 1) {
        if (tid < s) rbuf[tid] += rbuf[tid + s];
        __syncthreads();
    }
    float inv = 1.0f / rbuf[0];

    float acc = 0.f;
#pragma unroll 8
    for (int t = 0; t < MAXLEN; ++t)
        acc += sa[t] * enc[((size_t)t * BATCH + b) * HID + k0 + tid];
    g_c[b * HID + k0 + tid] = acc * inv;
}

// x = [embedding[cur], c]   (64 x 1536)
__global__ __launch_bounds__(256) void build_x_kernel(
    const int* __restrict__ cur, const float* __restrict__ embedding)
{
    int i = blockIdx.x * 256 + threadIdx.x;   // < 98304
    int b = i / XDIM;
    int q = i - b * XDIM;
    g_x[i] = (q < EMBED) ? embedding[(size_t)cur[b] * EMBED + q]
                         : g_c[b * HID + (q - EMBED)];
}

// ===========================================================================
// C = A @ B^T (+bias).  A: 64xK, B: NxK, row-major. Tile 64x64. N-guarded.
// A/C selected by tag IN DEVICE CODE so scratch globals never cross host ABI.
// ===========================================================================
__global__ __launch_bounds__(256) void gemm64_kernel(
    const float* __restrict__ Ap, int K, const float* __restrict__ B,
    const float* __restrict__ bias, float* __restrict__ Cp, int N,
    int atag, int ctag)
{
    const float* A = (atag == BUF_X)  ? g_x
                   : (atag == BUF_H0) ? g_h0
                   : (atag == BUF_H1) ? g_h1 : Ap;
    float* C = (ctag == BUF_GI) ? g_gi
             : (ctag == BUF_GH) ? g_gh : Cp;

    int n0 = blockIdx.x * 64;
    __shared__ float sA[64][65];   // [row][k]
    __shared__ float sB[64][65];   // [k][n]
    int tid = threadIdx.x;
    int tx = tid & 15;
    int ty = tid >> 4;
    float acc[4][4];
#pragma unroll
    for (int i = 0; i < 4; ++i)
#pragma unroll
        for (int j = 0; j < 4; ++j) acc[i][j] = 0.f;

    for (int kk0 = 0; kk0 < K; kk0 += 64) {
        for (int i = tid; i < 64 * 64; i += 256) {
            int r = i >> 6;
            int c = i & 63;
            sA[r][c] = A[(size_t)r * K + kk0 + c];
            int n = n0 + r;
            sB[c][r] = (n < N) ? B[(size_t)n * K + kk0 + c] : 0.f;
        }
        __syncthreads();
#pragma unroll 8
        for (int k = 0; k < 64; ++k) {
            float a0 = sA[ty * 4 + 0][k];
            float a1 = sA[ty * 4 + 1][k];
            float a2 = sA[ty * 4 + 2][k];
            float a3 = sA[ty * 4 + 3][k];
            float b0 = sB[k][tx * 4 + 0];
            float b1 = sB[k][tx * 4 + 1];
            float b2 = sB[k][tx * 4 + 2];
            float b3 = sB[k][tx * 4 + 3];
            acc[0][0] += a0 * b0; acc[0][1] += a0 * b1; acc[0][2] += a0 * b2; acc[0][3] += a0 * b3;
            acc[1][0] += a1 * b0; acc[1][1] += a1 * b1; acc[1][2] += a1 * b2; acc[1][3] += a1 * b3;
            acc[2][0] += a2 * b0; acc[2][1] += a2 * b1; acc[2][2] += a2 * b2; acc[2][3] += a2 * b3;
            acc[3][0] += a3 * b0; acc[3][1] += a3 * b1; acc[3][2] += a3 * b2; acc[3][3] += a3 * b3;
        }
        __syncthreads();
    }
#pragma unroll
    for (int i = 0; i < 4; ++i) {
        int row = ty * 4 + i;
#pragma unroll
        for (int j = 0; j < 4; ++j) {
            int n = n0 + tx * 4 + j;
            if (n < N)
                C[(size_t)row * N + n] = acc[i][j] + (bias ? bias[n] : 0.f);
        }
    }
}

// GRU combine: h' = (1-z)*n + z*h.  Output buffer chosen by tag in device code.
__global__ __launch_bounds__(256) void combine_kernel(
    const float* __restrict__ bih, const float* __restrict__ bhh,
    const float* __restrict__ hprev, int htag)
{
    float* hout = (htag == 0) ? g_h0 : g_h1;
    int i = blockIdx.x * 256 + threadIdx.x;   // < 65536
    int b = i >> 10, j = i & 1023;
    const float* gi = g_gi + b * G3;
    const float* gh = g_gh + b * G3;
    float r = 1.f / (1.f + expf(-((gi[j] + bih[j]) + (gh[j] + bhh[j]))));
    float z = 1.f / (1.f + expf(-((gi[HID + j] + bih[HID + j]) + (gh[HID + j] + bhh[HID + j]))));
    float n = tanhf((gi[2 * HID + j] + bih[2 * HID + j]) + r * (gh[2 * HID + j] + bhh[2 * HID + j]));
    hout[i] = (1.f - z) * n + z * hprev[i];
}

// copy [h0 | h1] into d_out's new_state region
__global__ __launch_bounds__(256) void copy_state_kernel(float* __restrict__ dst)
{
    int i = blockIdx.x * 256 + threadIdx.x;   // < 131072
    dst[i] = (i < BATCH * HID) ? g_h0[i] : g_h1[i - BATCH * HID];
}

// ===========================================================================
extern "C" void kernel_launch(void* const* d_in, const int* in_sizes, int n_in,
                              void* d_out, int out_size)
{
    // dict/signature order (confirmed: in_sizes[0]==64 both prior rounds)
    int I_cur, I_state, I_enc, I_emb, I_wa1, I_wa2, I_wih0, I_whh0, I_bih0,
        I_bhh0, I_wih1, I_whh1, I_bih1, I_bhh1, I_wout, I_bout;
    if (in_sizes[0] == 64) {
        I_cur = 0;  I_state = 1;  I_enc = 2;   I_emb = 3;
        I_wa1 = 4;  I_wa2 = 5;    I_wih0 = 6;  I_whh0 = 7;
        I_bih0 = 8; I_bhh0 = 9;   I_wih1 = 10; I_whh1 = 11;
        I_bih1 = 12; I_bhh1 = 13; I_wout = 14; I_bout = 15;
    } else {
        I_bhh0 = 0; I_bhh1 = 1;  I_bih0 = 2;  I_bih1 = 3;
        I_bout = 4; I_cur = 5;   I_emb = 6;   I_enc = 7;
        I_state = 8; I_wa1 = 9;  I_wa2 = 10;  I_whh0 = 11;
        I_whh1 = 12; I_wih0 = 13; I_wih1 = 14; I_wout = 15;
    }

    const int*   cur    = (const int*)  d_in[I_cur];
    const float* state  = (const float*)d_in[I_state];
    const float* enc    = (const float*)d_in[I_enc];
    const float* embed  = (const float*)d_in[I_emb];
    const float* w_att1 = (const float*)d_in[I_wa1];
    const float* w_att2 = (const float*)d_in[I_wa2];
    const float* w_ih0  = (const float*)d_in[I_wih0];
    const float* w_hh0  = (const float*)d_in[I_whh0];
    const float* b_ih0  = (const float*)d_in[I_bih0];
    const float* b_hh0  = (const float*)d_in[I_bhh0];
    const float* w_ih1  = (const float*)d_in[I_wih1];
    const float* w_hh1  = (const float*)d_in[I_whh1];
    const float* b_ih1  = (const float*)d_in[I_bih1];
    const float* b_hh1  = (const float*)d_in[I_bhh1];
    const float* w_out  = (const float*)d_in[I_wout];
    const float* b_out  = (const float*)d_in[I_bout];
    float* out = (float*)d_out;

    const float* state0 = state;
    const float* state1 = state + BATCH * HID;

    // ---------------- attention ----------------
    db_kernel<<<256, 256>>>(state, w_att1);
    scores_kernel<<<dim3(NPART, MAXLEN), 256>>>(enc, w_att1, w_att2);
    softmax_ctx_kernel<<<dim3(4, BATCH), 256>>>(enc);
    build_x_kernel<<<(BATCH * XDIM) / 256, 256>>>(cur, embed);

    // ---------------- GRU layer 0 ----------------
    gemm64_kernel<<<G3 / 64, 256>>>(nullptr, XDIM, w_ih0, nullptr, nullptr, G3, BUF_X,  BUF_GI);
    gemm64_kernel<<<G3 / 64, 256>>>(state0,  HID,  w_hh0, nullptr, nullptr, G3, BUF_PARAM, BUF_GH);
    combine_kernel<<<(BATCH * HID) / 256, 256>>>(b_ih0, b_hh0, state0, 0);

    // ---------------- GRU layer 1 ----------------
    gemm64_kernel<<<G3 / 64, 256>>>(nullptr, HID,  w_ih1, nullptr, nullptr, G3, BUF_H0, BUF_GI);
    gemm64_kernel<<<G3 / 64, 256>>>(state1,  HID,  w_hh1, nullptr, nullptr, G3, BUF_PARAM, BUF_GH);
    combine_kernel<<<(BATCH * HID) / 256, 256>>>(b_ih1, b_hh1, state1, 1);

    // ---------------- vocab projection ----------------
    gemm64_kernel<<<(VOCAB + 63) / 64, 256>>>(nullptr, HID, w_out, b_out, out, VOCAB, BUF_H1, BUF_PARAM);

    // ---------------- new_state (only if d_out has room) ----------------
    if (out_size >= OUT_OFF + 2 * BATCH * HID)
        copy_state_kernel<<<(2 * BATCH * HID) / 256, 256>>>(out + OUT_OFF);
}

// round 6
// speedup vs baseline: 4.3459x; 4.3459x over previous
#include <cuda_runtime.h>

#define BATCH   64
#define HID     1024
#define EMBED   512
#define MAXLEN  1024
#define VOCAB   50257
#define XDIM    (EMBED + HID)      // 1536
#define G3      (3 * HID)          // 3072
#define OUT_OFF (BATCH * VOCAB)    // 3216448
#define NPART   8                  // j-chunks (128 wide) for attention scores
#define NROWS   (MAXLEN * BATCH)   // 65536 rows of the big scores GEMM

// ------------- scratch (device globals; NEVER passed from host) -------------
__device__ float g_db[BATCH * HID];
__device__ float g_e_part[NPART * NROWS];
__device__ float g_c[BATCH * HID];
__device__ float g_x[BATCH * XDIM];
__device__ float g_gi[BATCH * G3];
__device__ float g_gh[BATCH * G3];
__device__ float g_h0[BATCH * HID];
__device__ float g_h1[BATCH * HID];

// buffer tags so scratch pointers are resolved IN DEVICE CODE
#define BUF_PARAM 0
#define BUF_X     1
#define BUF_H0    2
#define BUF_H1    3
#define BUF_GI    1
#define BUF_GH    2

// ---------------- small PTX helpers ----------------
__device__ __forceinline__ unsigned cvt_tf32(float x) {
    unsigned r;
    asm("cvt.rna.tf32.f32 %0, %1;\n" : "=r"(r) : "f"(x));
    return r;
}
__device__ __forceinline__ void mma_tf32(float* c, const unsigned* a,
                                         unsigned b0, unsigned b1) {
    asm volatile(
        "mma.sync.aligned.m16n8k8.row.col.f32.tf32.tf32.f32 "
        "{%0,%1,%2,%3}, {%4,%5,%6,%7}, {%8,%9}, {%0,%1,%2,%3};\n"
        : "+f"(c[0]), "+f"(c[1]), "+f"(c[2]), "+f"(c[3])
        : "r"(a[0]), "r"(a[1]), "r"(a[2]), "r"(a[3]), "r"(b0), "r"(b1));
}
__device__ __forceinline__ void cp16(float* s, const float* g) {
    unsigned sa = (unsigned)__cvta_generic_to_shared(s);
    asm volatile("cp.async.ca.shared.global [%0], [%1], 16;\n" :: "r"(sa), "l"(g));
}

// ===========================================================================
// db[b][j] = sum_k dec[b][k] * w1d[k][j]
// ===========================================================================
__global__ __launch_bounds__(256) void db_kernel(
    const float* __restrict__ state, const float* __restrict__ w_att1)
{
    int idx = blockIdx.x * 256 + threadIdx.x;   // 0..65535
    int b = idx >> 10;
    int j = idx & 1023;
    const float* dec = state + BATCH * HID;
    const float* w1d = w_att1 + (size_t)HID * HID;
    float acc = 0.f;
#pragma unroll 8
    for (int k = 0; k < HID; ++k)
        acc += dec[b * HID + k] * w1d[(size_t)k * HID + j];
    g_db[idx] = acc;
}

// ===========================================================================
// Tensor-core attention scores.
// One big GEMM: rows r = t*64+b (enc is contiguous over (t,b)), cols j, K=1024.
// CTA tile 128x128, BK=16, cp.async double-buffer, mma.m16n8k8.tf32.
// Epilogue: e_part[jc][r] = sum_{j in chunk} w2[j]*tanh(S[r][j] + db[b][j]).
// smem pool layout (floats): A0[0,2560) B0[2560,4736) A1[4736,7296) B1[7296,9472)
//   A stride 20 (16+4), B stride 136 (128+8)  -> conflict-free fragment reads.
//   db overlay (64 x stride 132 = 8448) reuses pool after the k-loop.
// ===========================================================================
#define SC_POOL 9472
__global__ __launch_bounds__(256) void scores_tc_kernel(
    const float* __restrict__ enc, const float* __restrict__ w_att1,
    const float* __restrict__ w_att2)
{
    __shared__ float pool[SC_POOL];
    __shared__ float red[2][128];
    __shared__ float w2s[128];

    const int tid    = threadIdx.x;
    const int lane   = tid & 31;
    const int wid    = tid >> 5;
    const int warp_m = wid >> 1;             // 0..3  (32-row band)
    const int warp_n = wid & 1;              // 0..1  (64-col band)
    const int j0     = blockIdx.x * 128;
    const int row0   = blockIdx.y * 128;

    if (tid < 128) w2s[tid] = w_att2[j0 + tid];

    float acc[2][8][4];                      // [mi][ni][reg]
#pragma unroll
    for (int mi = 0; mi < 2; ++mi)
#pragma unroll
        for (int ni = 0; ni < 8; ++ni)
#pragma unroll
            for (int r = 0; r < 4; ++r) acc[mi][ni][r] = 0.f;

    float* bufA0 = pool;
    float* bufB0 = pool + 2560;
    float* bufA1 = pool + 4736;
    float* bufB1 = pool + 7296;

    // ---- async load of one K-chunk (16 wide) into buffer `buf` ----
    auto issue = [&](int kk, int buf) {
        float* A = buf ? bufA1 : bufA0;
        float* B = buf ? bufB1 : bufB0;
#pragma unroll
        for (int it = 0; it < 2; ++it) {
            int idx = tid + it * 256;                 // 0..511
            int m  = idx >> 2, kq = (idx & 3) << 2;   // A: 128 rows x 16k
            cp16(A + m * 20 + kq,
                 enc + (size_t)(row0 + m) * HID + kk + kq);
            int k  = idx >> 5, jq = (idx & 31) << 2;  // B: 16 k x 128 j
            cp16(B + k * 136 + jq,
                 w_att1 + (size_t)(kk + k) * HID + j0 + jq);
        }
        asm volatile("cp.async.commit_group;\n");
    };

    auto compute = [&](int buf) {
        const float* A = buf ? bufA1 : bufA0;
        const float* B = buf ? bufB1 : bufB0;
#pragma unroll
        for (int ks = 0; ks < 2; ++ks) {
            const int kb = ks * 8;
            unsigned aR[2][4];
#pragma unroll
            for (int mi = 0; mi < 2; ++mi) {
                const float* ab = A + (warp_m * 32 + mi * 16 + (lane >> 2)) * 20
                                    + kb + (lane & 3);
                aR[mi][0] = cvt_tf32(ab[0]);
                aR[mi][1] = cvt_tf32(ab[8 * 20]);
                aR[mi][2] = cvt_tf32(ab[4]);
                aR[mi][3] = cvt_tf32(ab[8 * 20 + 4]);
            }
#pragma unroll
            for (int ni = 0; ni < 8; ++ni) {
                const float* bb = B + (kb + (lane & 3)) * 136
                                    + warp_n * 64 + ni * 8 + (lane >> 2);
                unsigned b0 = cvt_tf32(bb[0]);
                unsigned b1 = cvt_tf32(bb[4 * 136]);
#pragma unroll
                for (int mi = 0; mi < 2; ++mi)
                    mma_tf32(acc[mi][ni], aR[mi], b0, b1);
            }
        }
    };

    // ---- pipelined main loop over K = 64 chunks of 16 ----
    issue(0, 0);
    for (int ic = 0; ic < 64; ++ic) {
        if (ic + 1 < 64) {
            issue((ic + 1) * 16, (ic + 1) & 1);
            asm volatile("cp.async.wait_group 1;\n");
        } else {
            asm volatile("cp.async.wait_group 0;\n");
        }
        __syncthreads();
        compute(ic & 1);
        __syncthreads();
    }

    // ---- epilogue: stage db tile into dead pool, fuse tanh-dot-w2 ----
    float* db_s = pool;                          // [64][stride 132]
#pragma unroll
    for (int it = 0; it < 8; ++it) {
        int idx = tid + it * 256;                // 0..2047 float4s
        int b = idx >> 5, j4 = (idx & 31) << 2;
        float4 v = *(const float4*)(g_db + b * HID + j0 + j4);
        *(float4*)(db_s + b * 132 + j4) = v;
    }
    __syncthreads();

#pragma unroll
    for (int mi = 0; mi < 2; ++mi) {
#pragma unroll
        for (int half = 0; half < 2; ++half) {
            int rloc = warp_m * 32 + mi * 16 + half * 8 + (lane >> 2);
            int b = rloc & 63;
            float s = 0.f;
#pragma unroll
            for (int ni = 0; ni < 8; ++ni) {
#pragma unroll
                for (int c2 = 0; c2 < 2; ++c2) {
                    int col = warp_n * 64 + ni * 8 + ((lane & 3) << 1) + c2;
                    float v = acc[mi][ni][half * 2 + c2];
                    s += w2s[col] * tanhf(v + db_s[b * 132 + col]);
                }
            }
            s += __shfl_xor_sync(0xFFFFFFFFu, s, 1);
            s += __shfl_xor_sync(0xFFFFFFFFu, s, 2);
            if ((lane & 3) == 0) red[warp_n][rloc] = s;
        }
    }
    __syncthreads();
    if (tid < 128)
        g_e_part[(size_t)blockIdx.x * NROWS + row0 + tid] =
            red[0][tid] + red[1][tid];
}

// ===========================================================================
// softmax over t (per b) + context c[b][k] = sum_t alpha[t][b]*enc[t][b][k]
// ===========================================================================
__global__ __launch_bounds__(256) void softmax_ctx_kernel(const float* __restrict__ enc)
{
    int b  = blockIdx.y;
    int k0 = blockIdx.x * 256;
    int tid = threadIdx.x;
    __shared__ float sa[MAXLEN];
    __shared__ float rbuf[256];

    float lm = -1e30f;
    for (int t = tid; t < MAXLEN; t += 256) {
        float v = 0.f;
#pragma unroll
        for (int p = 0; p < NPART; ++p)
            v += g_e_part[(size_t)p * NROWS + t * BATCH + b];
        sa[t] = v;
        lm = fmaxf(lm, v);
    }
    rbuf[tid] = lm; __syncthreads();
    for (int s = 128; s > 0; s >>= 1) {
        if (tid < s) rbuf[tid] = fmaxf(rbuf[tid], rbuf[tid + s]);
        __syncthreads();
    }
    float m = rbuf[0];
    __syncthreads();

    float ls = 0.f;
    for (int t = tid; t < MAXLEN; t += 256) {
        float v = expf(sa[t] - m);
        sa[t] = v;
        ls += v;
    }
    rbuf[tid] = ls; __syncthreads();
    for (int s = 128; s > 0; s >>= 1) {
        if (tid < s) rbuf[tid] += rbuf[tid + s];
        __syncthreads();
    }
    float inv = 1.0f / rbuf[0];

    float acc = 0.f;
#pragma unroll 8
    for (int t = 0; t < MAXLEN; ++t)
        acc += sa[t] * enc[((size_t)t * BATCH + b) * HID + k0 + tid];
    g_c[b * HID + k0 + tid] = acc * inv;
}

// x = [embedding[cur], c]   (64 x 1536)
__global__ __launch_bounds__(256) void build_x_kernel(
    const int* __restrict__ cur, const float* __restrict__ embedding)
{
    int i = blockIdx.x * 256 + threadIdx.x;   // < 98304
    int b = i / XDIM;
    int q = i - b * XDIM;
    g_x[i] = (q < EMBED) ? embedding[(size_t)cur[b] * EMBED + q]
                         : g_c[b * HID + (q - EMBED)];
}

// ===========================================================================
// C = A @ B^T (+bias).  A: 64xK, B: NxK, row-major. Tile 64x64. N-guarded.
// ===========================================================================
__global__ __launch_bounds__(256) void gemm64_kernel(
    const float* __restrict__ Ap, int K, const float* __restrict__ B,
    const float* __restrict__ bias, float* __restrict__ Cp, int N,
    int atag, int ctag)
{
    const float* A = (atag == BUF_X)  ? g_x
                   : (atag == BUF_H0) ? g_h0
                   : (atag == BUF_H1) ? g_h1 : Ap;
    float* C = (ctag == BUF_GI) ? g_gi
             : (ctag == BUF_GH) ? g_gh : Cp;

    int n0 = blockIdx.x * 64;
    __shared__ float sA[64][65];
    __shared__ float sB[64][65];
    int tid = threadIdx.x;
    int tx = tid & 15;
    int ty = tid >> 4;
    float acc[4][4];
#pragma unroll
    for (int i = 0; i < 4; ++i)
#pragma unroll
        for (int j = 0; j < 4; ++j) acc[i][j] = 0.f;

    for (int kk0 = 0; kk0 < K; kk0 += 64) {
        for (int i = tid; i < 64 * 64; i += 256) {
            int r = i >> 6;
            int c = i & 63;
            sA[r][c] = A[(size_t)r * K + kk0 + c];
            int n = n0 + r;
            sB[c][r] = (n < N) ? B[(size_t)n * K + kk0 + c] : 0.f;
        }
        __syncthreads();
#pragma unroll 8
        for (int k = 0; k < 64; ++k) {
            float a0 = sA[ty * 4 + 0][k];
            float a1 = sA[ty * 4 + 1][k];
            float a2 = sA[ty * 4 + 2][k];
            float a3 = sA[ty * 4 + 3][k];
            float b0 = sB[k][tx * 4 + 0];
            float b1 = sB[k][tx * 4 + 1];
            float b2 = sB[k][tx * 4 + 2];
            float b3 = sB[k][tx * 4 + 3];
            acc[0][0] += a0 * b0; acc[0][1] += a0 * b1; acc[0][2] += a0 * b2; acc[0][3] += a0 * b3;
            acc[1][0] += a1 * b0; acc[1][1] += a1 * b1; acc[1][2] += a1 * b2; acc[1][3] += a1 * b3;
            acc[2][0] += a2 * b0; acc[2][1] += a2 * b1; acc[2][2] += a2 * b2; acc[2][3] += a2 * b3;
            acc[3][0] += a3 * b0; acc[3][1] += a3 * b1; acc[3][2] += a3 * b2; acc[3][3] += a3 * b3;
        }
        __syncthreads();
    }
#pragma unroll
    for (int i = 0; i < 4; ++i) {
        int row = ty * 4 + i;
#pragma unroll
        for (int j = 0; j < 4; ++j) {
            int n = n0 + tx * 4 + j;
            if (n < N)
                C[(size_t)row * N + n] = acc[i][j] + (bias ? bias[n] : 0.f);
        }
    }
}

// GRU combine: h' = (1-z)*n + z*h
__global__ __launch_bounds__(256) void combine_kernel(
    const float* __restrict__ bih, const float* __restrict__ bhh,
    const float* __restrict__ hprev, int htag)
{
    float* hout = (htag == 0) ? g_h0 : g_h1;
    int i = blockIdx.x * 256 + threadIdx.x;   // < 65536
    int b = i >> 10, j = i & 1023;
    const float* gi = g_gi + b * G3;
    const float* gh = g_gh + b * G3;
    float r = 1.f / (1.f + expf(-((gi[j] + bih[j]) + (gh[j] + bhh[j]))));
    float z = 1.f / (1.f + expf(-((gi[HID + j] + bih[HID + j]) + (gh[HID + j] + bhh[HID + j]))));
    float n = tanhf((gi[2 * HID + j] + bih[2 * HID + j]) + r * (gh[2 * HID + j] + bhh[2 * HID + j]));
    hout[i] = (1.f - z) * n + z * hprev[i];
}

// copy [h0 | h1] into d_out's new_state region
__global__ __launch_bounds__(256) void copy_state_kernel(float* __restrict__ dst)
{
    int i = blockIdx.x * 256 + threadIdx.x;   // < 131072
    dst[i] = (i < BATCH * HID) ? g_h0[i] : g_h1[i - BATCH * HID];
}

// ===========================================================================
extern "C" void kernel_launch(void* const* d_in, const int* in_sizes, int n_in,
                              void* d_out, int out_size)
{
    int I_cur, I_state, I_enc, I_emb, I_wa1, I_wa2, I_wih0, I_whh0, I_bih0,
        I_bhh0, I_wih1, I_whh1, I_bih1, I_bhh1, I_wout, I_bout;
    if (in_sizes[0] == 64) {
        I_cur = 0;  I_state = 1;  I_enc = 2;   I_emb = 3;
        I_wa1 = 4;  I_wa2 = 5;    I_wih0 = 6;  I_whh0 = 7;
        I_bih0 = 8; I_bhh0 = 9;   I_wih1 = 10; I_whh1 = 11;
        I_bih1 = 12; I_bhh1 = 13; I_wout = 14; I_bout = 15;
    } else {
        I_bhh0 = 0; I_bhh1 = 1;  I_bih0 = 2;  I_bih1 = 3;
        I_bout = 4; I_cur = 5;   I_emb = 6;   I_enc = 7;
        I_state = 8; I_wa1 = 9;  I_wa2 = 10;  I_whh0 = 11;
        I_whh1 = 12; I_wih0 = 13; I_wih1 = 14; I_wout = 15;
    }

    const int*   cur    = (const int*)  d_in[I_cur];
    const float* state  = (const float*)d_in[I_state];
    const float* enc    = (const float*)d_in[I_enc];
    const float* embed  = (const float*)d_in[I_emb];
    const float* w_att1 = (const float*)d_in[I_wa1];
    const float* w_att2 = (const float*)d_in[I_wa2];
    const float* w_ih0  = (const float*)d_in[I_wih0];
    const float* w_hh0  = (const float*)d_in[I_whh0];
    const float* b_ih0  = (const float*)d_in[I_bih0];
    const float* b_hh0  = (const float*)d_in[I_bhh0];
    const float* w_ih1  = (const float*)d_in[I_wih1];
    const float* w_hh1  = (const float*)d_in[I_whh1];
    const float* b_ih1  = (const float*)d_in[I_bih1];
    const float* b_hh1  = (const float*)d_in[I_bhh1];
    const float* w_out  = (const float*)d_in[I_wout];
    const float* b_out  = (const float*)d_in[I_bout];
    float* out = (float*)d_out;

    const float* state0 = state;
    const float* state1 = state + BATCH * HID;

    // ---------------- attention ----------------
    db_kernel<<<256, 256>>>(state, w_att1);
    scores_tc_kernel<<<dim3(NPART, NROWS / 128), 256>>>(enc, w_att1, w_att2);
    softmax_ctx_kernel<<<dim3(4, BATCH), 256>>>(enc);
    build_x_kernel<<<(BATCH * XDIM) / 256, 256>>>(cur, embed);

    // ---------------- GRU layer 0 ----------------
    gemm64_kernel<<<G3 / 64, 256>>>(nullptr, XDIM, w_ih0, nullptr, nullptr, G3, BUF_X,  BUF_GI);
    gemm64_kernel<<<G3 / 64, 256>>>(state0,  HID,  w_hh0, nullptr, nullptr, G3, BUF_PARAM, BUF_GH);
    combine_kernel<<<(BATCH * HID) / 256, 256>>>(b_ih0, b_hh0, state0, 0);

    // ---------------- GRU layer 1 ----------------
    gemm64_kernel<<<G3 / 64, 256>>>(nullptr, HID,  w_ih1, nullptr, nullptr, G3, BUF_H0, BUF_GI);
    gemm64_kernel<<<G3 / 64, 256>>>(state1,  HID,  w_hh1, nullptr, nullptr, G3, BUF_PARAM, BUF_GH);
    combine_kernel<<<(BATCH * HID) / 256, 256>>>(b_ih1, b_hh1, state1, 1);

    // ---------------- vocab projection ----------------
    gemm64_kernel<<<(VOCAB + 63) / 64, 256>>>(nullptr, HID, w_out, b_out, out, VOCAB, BUF_H1, BUF_PARAM);

    // ---------------- new_state ----------------
    if (out_size >= OUT_OFF + 2 * BATCH * HID)
        copy_state_kernel<<<(2 * BATCH * HID) / 256, 256>>>(out + OUT_OFF);
}

// round 9
// speedup vs baseline: 5.2878x; 1.2167x over previous
#include <cuda_runtime.h>

#define BATCH   64
#define HID     1024
#define EMBED   512
#define MAXLEN  1024
#define VOCAB   50257
#define XDIM    (EMBED + HID)      // 1536
#define G3      (3 * HID)          // 3072
#define OUT_OFF (BATCH * VOCAB)    // 3216448
#define NPART   8                  // j-chunks (128 wide) for attention scores
#define NROWS   (MAXLEN * BATCH)   // 65536 rows of the big scores GEMM

// ------------- scratch (device globals; NEVER passed from host) -------------
__device__ float g_db[BATCH * HID];
__device__ float g_e_part[NPART * NROWS];
__device__ float g_c[BATCH * HID];
__device__ float g_x[BATCH * XDIM];
__device__ float g_gi[BATCH * G3];
__device__ float g_gh[BATCH * G3];
__device__ float g_h0[BATCH * HID];
__device__ float g_h1[BATCH * HID];

// buffer tags so scratch pointers are resolved IN DEVICE CODE
#define BUF_PARAM 0
#define BUF_X     1
#define BUF_H0    2
#define BUF_H1    3
// C-side tags
#define CT_PARAM  0
#define CT_GI     1
#define CT_GH     2
#define CT_DB     3

// ---------------- small PTX helpers ----------------
__device__ __forceinline__ unsigned cvt_tf32(float x) {
    unsigned r;
    asm("cvt.rna.tf32.f32 %0, %1;\n" : "=r"(r) : "f"(x));
    return r;
}
// 3xTF32 split: a = hi + lo, both tf32-representable; a-hi exact in fp32.
__device__ __forceinline__ void split_tf32(float f, unsigned& hi, unsigned& lo) {
    unsigned h = cvt_tf32(f);
    float r = f - __uint_as_float(h);
    hi = h;
    lo = cvt_tf32(r);
}
__device__ __forceinline__ void mma_tf32(float* c, const unsigned* a,
                                         unsigned b0, unsigned b1) {
    asm volatile(
        "mma.sync.aligned.m16n8k8.row.col.f32.tf32.tf32.f32 "
        "{%0,%1,%2,%3}, {%4,%5,%6,%7}, {%8,%9}, {%0,%1,%2,%3};\n"
        : "+f"(c[0]), "+f"(c[1]), "+f"(c[2]), "+f"(c[3])
        : "r"(a[0]), "r"(a[1]), "r"(a[2]), "r"(a[3]), "r"(b0), "r"(b1));
}
__device__ __forceinline__ void cp16(float* s, const float* g) {
    unsigned sa = (unsigned)__cvta_generic_to_shared(s);
    asm volatile("cp.async.ca.shared.global [%0], [%1], 16;\n" :: "r"(sa), "l"(g));
}

// ===========================================================================
// Tensor-core attention scores (single tf32 with cvt.rna — round-6-proven).
// rows r = t*64+b, cols j, K=1024. CTA tile 128x128, BK=16, double-buffer,
// one __syncthreads per K-chunk.
// pool floats: A0[0,2560) B0[2560,4736) A1[4736,7296) B1[7296,9472)
// A stride 20, B stride 136. db overlay (64 x 132) reuses pool afterwards.
// ===========================================================================
#define SC_POOL 9472
__global__ __launch_bounds__(256) void scores_tc_kernel(
    const float* __restrict__ enc, const float* __restrict__ w_att1,
    const float* __restrict__ w_att2)
{
    __shared__ float pool[SC_POOL];
    __shared__ float red[2][128];
    __shared__ float w2s[128];

    const int tid    = threadIdx.x;
    const int lane   = tid & 31;
    const int wid    = tid >> 5;
    const int warp_m = wid >> 1;             // 0..3  (32-row band)
    const int warp_n = wid & 1;              // 0..1  (64-col band)
    const int j0     = blockIdx.x * 128;
    const int row0   = blockIdx.y * 128;

    if (tid < 128) w2s[tid] = w_att2[j0 + tid];

    float acc[2][8][4];
#pragma unroll
    for (int mi = 0; mi < 2; ++mi)
#pragma unroll
        for (int ni = 0; ni < 8; ++ni)
#pragma unroll
            for (int r = 0; r < 4; ++r) acc[mi][ni][r] = 0.f;

    float* bufA0 = pool;
    float* bufB0 = pool + 2560;
    float* bufA1 = pool + 4736;
    float* bufB1 = pool + 7296;

    auto issue = [&](int kk, int buf) {
        float* A = buf ? bufA1 : bufA0;
        float* B = buf ? bufB1 : bufB0;
#pragma unroll
        for (int it = 0; it < 2; ++it) {
            int idx = tid + it * 256;                 // 0..511
            int m  = idx >> 2, kq = (idx & 3) << 2;   // A: 128 rows x 16k
            cp16(A + m * 20 + kq,
                 enc + (size_t)(row0 + m) * HID + kk + kq);
            int k  = idx >> 5, jq = (idx & 31) << 2;  // B: 16k x 128 j
            cp16(B + k * 136 + jq,
                 w_att1 + (size_t)(kk + k) * HID + j0 + jq);
        }
        asm volatile("cp.async.commit_group;\n");
    };

    auto compute = [&](int buf) {
        const float* A = buf ? bufA1 : bufA0;
        const float* B = buf ? bufB1 : bufB0;
#pragma unroll
        for (int ks = 0; ks < 2; ++ks) {
            const int kb = ks * 8;
            unsigned aR[2][4];
#pragma unroll
            for (int mi = 0; mi < 2; ++mi) {
                const float* ab = A + (warp_m * 32 + mi * 16 + (lane >> 2)) * 20
                                    + kb + (lane & 3);
                aR[mi][0] = cvt_tf32(ab[0]);
                aR[mi][1] = cvt_tf32(ab[8 * 20]);
                aR[mi][2] = cvt_tf32(ab[4]);
                aR[mi][3] = cvt_tf32(ab[8 * 20 + 4]);
            }
#pragma unroll
            for (int ni = 0; ni < 8; ++ni) {
                const float* bb = B + (kb + (lane & 3)) * 136
                                    + warp_n * 64 + ni * 8 + (lane >> 2);
                unsigned b0 = cvt_tf32(bb[0]);
                unsigned b1 = cvt_tf32(bb[4 * 136]);
#pragma unroll
                for (int mi = 0; mi < 2; ++mi)
                    mma_tf32(acc[mi][ni], aR[mi], b0, b1);
            }
        }
    };

    // ---- pipelined loop: wait -> sync -> prefetch next -> compute ----
    issue(0, 0);
    for (int ic = 0; ic < 64; ++ic) {
        asm volatile("cp.async.wait_group 0;\n");
        __syncthreads();                         // data(ic) visible; buf(ic+1) free
        if (ic + 1 < 64) issue((ic + 1) * 16, (ic + 1) & 1);
        compute(ic & 1);
    }
    __syncthreads();                             // all warps done with pool

    // ---- epilogue: stage db tile into dead pool, fuse tanh-dot-w2 ----
    float* db_s = pool;                          // [64][stride 132]
#pragma unroll
    for (int it = 0; it < 8; ++it) {
        int idx = tid + it * 256;                // 0..2047 float4s
        int b = idx >> 5, j4 = (idx & 31) << 2;
        float4 v = *(const float4*)(g_db + b * HID + j0 + j4);
        *(float4*)(db_s + b * 132 + j4) = v;
    }
    __syncthreads();

#pragma unroll
    for (int mi = 0; mi < 2; ++mi) {
#pragma unroll
        for (int half = 0; half < 2; ++half) {
            int rloc = warp_m * 32 + mi * 16 + half * 8 + (lane >> 2);
            int b = rloc & 63;
            float s = 0.f;
#pragma unroll
            for (int ni = 0; ni < 8; ++ni) {
#pragma unroll
                for (int c2 = 0; c2 < 2; ++c2) {
                    int col = warp_n * 64 + ni * 8 + ((lane & 3) << 1) + c2;
                    float v = acc[mi][ni][half * 2 + c2];
                    s += w2s[col] * tanhf(v + db_s[b * 132 + col]);
                }
            }
            s += __shfl_xor_sync(0xFFFFFFFFu, s, 1);
            s += __shfl_xor_sync(0xFFFFFFFFu, s, 2);
            if ((lane & 3) == 0) red[warp_n][rloc] = s;
        }
    }
    __syncthreads();
    if (tid < 128)
        g_e_part[(size_t)blockIdx.x * NROWS + row0 + tid] =
            red[0][tid] + red[1][tid];
}

// ===========================================================================
// Compensated (3xTF32) tensor-core GEMM, C(64 x N) = A(64 x K) @ op(B) (+bias)
// Near-fp32 accuracy: C = Ahi*Bhi + Ahi*Blo + Alo*Bhi.
// TRANSB=1: B is [N][K] (C = A@B^T); TRANSB=0: B is [K][N] (C = A@B).
// CTA tile 64 x 128, BK=16, cp.async double-buffer.
// ===========================================================================
template <int TRANSB>
__global__ __launch_bounds__(256) void tc_gemm_kernel(
    const float* __restrict__ Ap, int K, const float* __restrict__ B,
    const float* __restrict__ bias, float* __restrict__ Cp, int N,
    int atag, int ctag)
{
    const float* A = (atag == BUF_X)  ? g_x
                   : (atag == BUF_H0) ? g_h0
                   : (atag == BUF_H1) ? g_h1 : Ap;
    float* C = (ctag == CT_GI) ? g_gi
             : (ctag == CT_GH) ? g_gh
             : (ctag == CT_DB) ? g_db : Cp;

    __shared__ float sA[2][64 * 20];             // 64 rows x 16k, stride 20
    __shared__ float sB[2][2560];                // TRANSB: 128n x 16k (stride 20)
                                                 // else:   16k x 128n (stride 136)
    const int tid    = threadIdx.x;
    const int lane   = tid & 31;
    const int wid    = tid >> 5;
    const int warp_m = wid & 1;                  // 2 bands x 32 rows
    const int warp_n = wid >> 1;                 // 4 bands x 32 cols
    const int j0     = blockIdx.x * 128;

    float acc[2][4][4];
#pragma unroll
    for (int mi = 0; mi < 2; ++mi)
#pragma unroll
        for (int ni = 0; ni < 4; ++ni)
#pragma unroll
            for (int r = 0; r < 4; ++r) acc[mi][ni][r] = 0.f;

    auto issue = [&](int kk, int buf) {
        {
            int m = tid >> 2, kq = (tid & 3) << 2;
            cp16(&sA[buf][m * 20 + kq], A + (size_t)m * K + kk + kq);
        }
#pragma unroll
        for (int it = 0; it < 2; ++it) {
            int idx = tid + it * 256;
            if (TRANSB) {
                int n = idx >> 2, kq = (idx & 3) << 2;
                int gn = j0 + n;
                if (gn < N) {
                    cp16(&sB[buf][n * 20 + kq], B + (size_t)gn * K + kk + kq);
                } else {
                    float4 z = make_float4(0.f, 0.f, 0.f, 0.f);
                    *(float4*)&sB[buf][n * 20 + kq] = z;
                }
            } else {
                int k = idx >> 5, jq = (idx & 31) << 2;
                cp16(&sB[buf][k * 136 + jq], B + (size_t)(kk + k) * N + j0 + jq);
            }
        }
        asm volatile("cp.async.commit_group;\n");
    };

    auto compute = [&](int buf) {
        const float* Ab = sA[buf];
        const float* Bb = sB[buf];
#pragma unroll
        for (int ks = 0; ks < 2; ++ks) {
            const int kb = ks * 8;
            unsigned aHi[2][4], aLo[2][4];
#pragma unroll
            for (int mi = 0; mi < 2; ++mi) {
                const float* ab = Ab + (warp_m * 32 + mi * 16 + (lane >> 2)) * 20
                                     + kb + (lane & 3);
                split_tf32(ab[0],          aHi[mi][0], aLo[mi][0]);
                split_tf32(ab[8 * 20],     aHi[mi][1], aLo[mi][1]);
                split_tf32(ab[4],          aHi[mi][2], aLo[mi][2]);
                split_tf32(ab[8 * 20 + 4], aHi[mi][3], aLo[mi][3]);
            }
#pragma unroll
            for (int ni = 0; ni < 4; ++ni) {
                int col = warp_n * 32 + ni * 8 + (lane >> 2);
                float bf0, bf1;
                if (TRANSB) {
                    bf0 = Bb[col * 20 + kb + (lane & 3)];
                    bf1 = Bb[col * 20 + kb + 4 + (lane & 3)];
                } else {
                    bf0 = Bb[(kb + (lane & 3)) * 136 + col];
                    bf1 = Bb[(kb + 4 + (lane & 3)) * 136 + col];
                }
                unsigned bHi0, bLo0, bHi1, bLo1;
                split_tf32(bf0, bHi0, bLo0);
                split_tf32(bf1, bHi1, bLo1);
#pragma unroll
                for (int mi = 0; mi < 2; ++mi) {
                    mma_tf32(acc[mi][ni], aHi[mi], bHi0, bHi1);
                    mma_tf32(acc[mi][ni], aHi[mi], bLo0, bLo1);
                    mma_tf32(acc[mi][ni], aLo[mi], bHi0, bHi1);
                }
            }
        }
    };

    const int nch = K >> 4;
    issue(0, 0);
    for (int ic = 0; ic < nch; ++ic) {
        asm volatile("cp.async.wait_group 0;\n");
        __syncthreads();
        if (ic + 1 < nch) issue((ic + 1) << 4, (ic + 1) & 1);
        compute(ic & 1);
    }

    // epilogue
#pragma unroll
    for (int mi = 0; mi < 2; ++mi) {
#pragma unroll
        for (int half = 0; half < 2; ++half) {
            int row = warp_m * 32 + mi * 16 + half * 8 + (lane >> 2);
#pragma unroll
            for (int ni = 0; ni < 4; ++ni) {
#pragma unroll
                for (int c2 = 0; c2 < 2; ++c2) {
                    int n = j0 + warp_n * 32 + ni * 8 + ((lane & 3) << 1) + c2;
                    if (n < N)
                        C[(size_t)row * N + n] = acc[mi][ni][half * 2 + c2]
                                               + (bias ? bias[n] : 0.f);
                }
            }
        }
    }
}

// ===========================================================================
// softmax over t (per b) + context c[b][k] = sum_t alpha[t][b]*enc[t][b][k]
// ===========================================================================
__global__ __launch_bounds__(256) void softmax_ctx_kernel(const float* __restrict__ enc)
{
    int b  = blockIdx.y;
    int k0 = blockIdx.x * 256;
    int tid = threadIdx.x;
    __shared__ float sa[MAXLEN];
    __shared__ float rbuf[256];

    float lm = -1e30f;
    for (int t = tid; t < MAXLEN; t += 256) {
        float v = 0.f;
#pragma unroll
        for (int p = 0; p < NPART; ++p)
            v += g_e_part[(size_t)p * NROWS + t * BATCH + b];
        sa[t] = v;
        lm = fmaxf(lm, v);
    }
    rbuf[tid] = lm; __syncthreads();
    for (int s = 128; s > 0; s >>= 1) {
        if (tid < s) rbuf[tid] = fmaxf(rbuf[tid], rbuf[tid + s]);
        __syncthreads();
    }
    float m = rbuf[0];
    __syncthreads();

    float ls = 0.f;
    for (int t = tid; t < MAXLEN; t += 256) {
        float v = expf(sa[t] - m);
        sa[t] = v;
        ls += v;
    }
    rbuf[tid] = ls; __syncthreads();
    for (int s = 128; s > 0; s >>= 1) {
        if (tid < s) rbuf[tid] += rbuf[tid + s];
        __syncthreads();
    }
    float inv = 1.0f / rbuf[0];

    float acc = 0.f;
#pragma unroll 8
    for (int t = 0; t < MAXLEN; ++t)
        acc += sa[t] * enc[((size_t)t * BATCH + b) * HID + k0 + tid];
    g_c[b * HID + k0 + tid] = acc * inv;
}

// x = [embedding[cur], c]   (64 x 1536)
__global__ __launch_bounds__(256) void build_x_kernel(
    const int* __restrict__ cur, const float* __restrict__ embedding)
{
    int i = blockIdx.x * 256 + threadIdx.x;   // < 98304
    int b = i / XDIM;
    int q = i - b * XDIM;
    g_x[i] = (q < EMBED) ? embedding[(size_t)cur[b] * EMBED + q]
                         : g_c[b * HID + (q - EMBED)];
}

// GRU combine: h' = (1-z)*n + z*h
__global__ __launch_bounds__(256) void combine_kernel(
    const float* __restrict__ bih, const float* __restrict__ bhh,
    const float* __restrict__ hprev, int htag)
{
    float* hout = (htag == 0) ? g_h0 : g_h1;
    int i = blockIdx.x * 256 + threadIdx.x;   // < 65536
    int b = i >> 10, j = i & 1023;
    const float* gi = g_gi + b * G3;
    const float* gh = g_gh + b * G3;
    float r = 1.f / (1.f + expf(-((gi[j] + bih[j]) + (gh[j] + bhh[j]))));
    float z = 1.f / (1.f + expf(-((gi[HID + j] + bih[HID + j]) + (gh[HID + j] + bhh[HID + j]))));
    float n = tanhf((gi[2 * HID + j] + bih[2 * HID + j]) + r * (gh[2 * HID + j] + bhh[2 * HID + j]));
    hout[i] = (1.f - z) * n + z * hprev[i];
}

// copy [h0 | h1] into d_out's new_state region
__global__ __launch_bounds__(256) void copy_state_kernel(float* __restrict__ dst)
{
    int i = blockIdx.x * 256 + threadIdx.x;   // < 131072
    dst[i] = (i < BATCH * HID) ? g_h0[i] : g_h1[i - BATCH * HID];
}

// ===========================================================================
extern "C" void kernel_launch(void* const* d_in, const int* in_sizes, int n_in,
                              void* d_out, int out_size)
{
    int I_cur, I_state, I_enc, I_emb, I_wa1, I_wa2, I_wih0, I_whh0, I_bih0,
        I_bhh0, I_wih1, I_whh1, I_bih1, I_bhh1, I_wout, I_bout;
    if (in_sizes[0] == 64) {
        I_cur = 0;  I_state = 1;  I_enc = 2;   I_emb = 3;
        I_wa1 = 4;  I_wa2 = 5;    I_wih0 = 6;  I_whh0 = 7;
        I_bih0 = 8; I_bhh0 = 9;   I_wih1 = 10; I_whh1 = 11;
        I_bih1 = 12; I_bhh1 = 13; I_wout = 14; I_bout = 15;
    } else {
        I_bhh0 = 0; I_bhh1 = 1;  I_bih0 = 2;  I_bih1 = 3;
        I_bout = 4; I_cur = 5;   I_emb = 6;   I_enc = 7;
        I_state = 8; I_wa1 = 9;  I_wa2 = 10;  I_whh0 = 11;
        I_whh1 = 12; I_wih0 = 13; I_wih1 = 14; I_wout = 15;
    }

    const int*   cur    = (const int*)  d_in[I_cur];
    const float* state  = (const float*)d_in[I_state];
    const float* enc    = (const float*)d_in[I_enc];
    const float* embed  = (const float*)d_in[I_emb];
    const float* w_att1 = (const float*)d_in[I_wa1];
    const float* w_att2 = (const float*)d_in[I_wa2];
    const float* w_ih0  = (const float*)d_in[I_wih0];
    const float* w_hh0  = (const float*)d_in[I_whh0];
    const float* b_ih0  = (const float*)d_in[I_bih0];
    const float* b_hh0  = (const float*)d_in[I_bhh0];
    const float* w_ih1  = (const float*)d_in[I_wih1];
    const float* w_hh1  = (const float*)d_in[I_whh1];
    const float* b_ih1  = (const float*)d_in[I_bih1];
    const float* b_hh1  = (const float*)d_in[I_bhh1];
    const float* w_out  = (const float*)d_in[I_wout];
    const float* b_out  = (const float*)d_in[I_bout];
    float* out = (float*)d_out;

    const float* dec = state + BATCH * HID;    // state[1]

    // ---------------- attention ----------------
    // db = dec @ w1_d   (A@B: w1_d is [K][N])
    tc_gemm_kernel<0><<<HID / 128, 256>>>(dec, HID, w_att1 + (size_t)HID * HID,
                                          nullptr, nullptr, HID, BUF_PARAM, CT_DB);
    scores_tc_kernel<<<dim3(NPART, NROWS / 128), 256>>>(enc, w_att1, w_att2);
    softmax_ctx_kernel<<<dim3(4, BATCH), 256>>>(enc);
    build_x_kernel<<<(BATCH * XDIM) / 256, 256>>>(cur, embed);

    // ---------------- GRU layer 0 ----------------
    tc_gemm_kernel<1><<<G3 / 128, 256>>>(nullptr, XDIM, w_ih0, nullptr, nullptr, G3, BUF_X, CT_GI);
    tc_gemm_kernel<1><<<G3 / 128, 256>>>(state,  HID,  w_hh0, nullptr, nullptr, G3, BUF_PARAM, CT_GH);
    combine_kernel<<<(BATCH * HID) / 256, 256>>>(b_ih0, b_hh0, state, 0);

    // ---------------- GRU layer 1 ----------------
    tc_gemm_kernel<1><<<G3 / 128, 256>>>(nullptr, HID, w_ih1, nullptr, nullptr, G3, BUF_H0, CT_GI);
    tc_gemm_kernel<1><<<G3 / 128, 256>>>(dec,     HID, w_hh1, nullptr, nullptr, G3, BUF_PARAM, CT_GH);
    combine_kernel<<<(BATCH * HID) / 256, 256>>>(b_ih1, b_hh1, dec, 1);

    // ---------------- vocab projection ----------------
    tc_gemm_kernel<1><<<(VOCAB + 127) / 128, 256>>>(nullptr, HID, w_out, b_out,
                                                    out, VOCAB, BUF_H1, CT_PARAM);

    // ---------------- new_state ----------------
    if (out_size >= OUT_OFF + 2 * BATCH * HID)
        copy_state_kernel<<<(2 * BATCH * HID) / 256, 256>>>(out + OUT_OFF);
}